// round 1
// baseline (speedup 1.0000x reference)
#include <cuda_runtime.h>
#include <math.h>

#define NB 128
#define NT 2048
#define NH 200
#define NH4 800
#define NSTEP 5

// ---- scratch (device globals: no allocations allowed) ----
__device__ float g_qproj[NB * NH];     // q@Wa.T + ba
__device__ float g_hpre[NB * NH4];     // q@W_hh.T + b_hh
__device__ float g_scores[NB * NT];    // attention scores
__device__ float g_context[NB * NH];   // attention context

__device__ __forceinline__ float sigm(float x) { return 1.f / (1.f + expf(-x)); }

// ============================================================================
// K1: q_proj[b,j] = ba[j] + sum_k h0[b,k] Wa[j,k]
//     h_pre[b,j4] = b_hh[j4] + sum_k h0[b,k] W_hh[j4,k]
// ============================================================================
__global__ void k_pre(const float* __restrict__ h0, const float* __restrict__ Wa,
                      const float* __restrict__ ba, const float* __restrict__ Whh,
                      const float* __restrict__ bhh) {
    int b = blockIdx.x, tid = threadIdx.x;
    __shared__ float hs[NH];
    if (tid < NH) hs[tid] = h0[b * NH + tid];
    __syncthreads();
    if (tid < NH) {
        float s = ba[tid];
        const float* w = Wa + tid * NH;
        #pragma unroll 4
        for (int k = 0; k < NH; k++) s = fmaf(hs[k], w[k], s);
        g_qproj[b * NH + tid] = s;
    }
    for (int j = tid; j < NH4; j += blockDim.x) {
        float s = bhh[j];
        const float* w = Whh + j * NH;
        #pragma unroll 4
        for (int k = 0; k < NH; k++) s = fmaf(hs[k], w[k], s);
        g_hpre[b * NH4 + j] = s;
    }
}

// ============================================================================
// K2: fused  kp = enc @ Ua.T (+bua+q_proj) -> tanh -> dot Va  => scores[b,t]
// CTA tile: 128 tokens x 208 (padded N) full-K GEMM; 256 threads;
// per-thread microtile 8 rows x 13 cols.
// ============================================================================
#define MT 128
#define KC 50
#define NP 208     // N padded (cols 200..207 are zero => contribute tanh(0)*0)
#define BSTR 209   // Ub row stride (odd => conflict-free transpose store)

#define SMEM_SCORES ((MT * NH + KC * BSTR + 2 * NP) * sizeof(float))

__global__ __launch_bounds__(256) void k_scores(
    const float* __restrict__ enc, const float* __restrict__ Ua,
    const float* __restrict__ bua, const float* __restrict__ Va,
    const float* __restrict__ bva) {
    extern __shared__ float sm[];
    float* As = sm;                    // [MT][NH]  = enc tile (row-major, contiguous copy)
    float* Ub = As + MT * NH;          // [KC][BSTR] = Ua^T chunk (padded)
    float* qb = Ub + KC * BSTR;        // [NP]  q_proj + bua (padded w/ 0)
    float* va = qb + NP;               // [NP]  Va (padded w/ 0)

    const int tile = blockIdx.x, b = blockIdx.y;
    const int tid = threadIdx.x, tx = tid & 15, ty = tid >> 4;
    const int t0 = tile * MT;

    // load enc tile: contiguous 128x200 block => fully coalesced copy
    const float* eb = enc + ((size_t)b * NT + t0) * NH;
    for (int i = tid; i < MT * NH; i += 256) As[i] = eb[i];
    for (int j = tid; j < NP; j += 256) {
        qb[j] = (j < NH) ? (g_qproj[b * NH + j] + bua[j]) : 0.f;
        va[j] = (j < NH) ? Va[j] : 0.f;
    }

    float acc[8][13];
    #pragma unroll
    for (int r = 0; r < 8; r++)
        #pragma unroll
        for (int c = 0; c < 13; c++) acc[r][c] = 0.f;

    for (int kc = 0; kc < NH; kc += KC) {
        __syncthreads();
        // transpose-load Ua chunk: read coalesced along k, store conflict-free
        for (int i = tid; i < NP * KC; i += 256) {
            int j = i / KC, k = i % KC;
            Ub[k * BSTR + j] = (j < NH) ? Ua[j * NH + kc + k] : 0.f;
        }
        __syncthreads();
        #pragma unroll 2
        for (int k = 0; k < KC; k++) {
            float bv[13];
            #pragma unroll
            for (int c = 0; c < 13; c++) bv[c] = Ub[k * BSTR + tx + 16 * c];
            #pragma unroll
            for (int r = 0; r < 8; r++) {
                float av = As[(ty * 8 + r) * NH + kc + k];
                #pragma unroll
                for (int c = 0; c < 13; c++) acc[r][c] = fmaf(av, bv[c], acc[r][c]);
            }
        }
    }

    // epilogue: e = tanh(kp + qb), score = sum va*e ; reduce over tx half-warps
    const float bv0 = bva[0];
    #pragma unroll
    for (int r = 0; r < 8; r++) {
        float s = 0.f;
        #pragma unroll
        for (int c = 0; c < 13; c++) {
            int j = tx + 16 * c;
            s = fmaf(va[j], tanhf(acc[r][c] + qb[j]), s);
        }
        #pragma unroll
        for (int off = 8; off; off >>= 1)
            s += __shfl_down_sync(0xffffffffu, s, off, 16);
        if (tx == 0)
            g_scores[(size_t)b * NT + t0 + ty * 8 + r] = s + bv0;
    }
}

// ============================================================================
// K3: per-b softmax over T + context[b,h] = sum_t attn[t] * enc[b,t,h]
// ============================================================================
__global__ void k_softctx(const float* __restrict__ enc) {
    int b = blockIdx.x, tid = threadIdx.x;
    __shared__ float at[NT];
    __shared__ float red[256];

    float m = -1e30f;
    for (int t = tid; t < NT; t += 256) {
        float s = g_scores[(size_t)b * NT + t];
        at[t] = s;
        m = fmaxf(m, s);
    }
    red[tid] = m; __syncthreads();
    for (int o = 128; o; o >>= 1) {
        if (tid < o) red[tid] = fmaxf(red[tid], red[tid + o]);
        __syncthreads();
    }
    m = red[0]; __syncthreads();

    float l = 0.f;
    for (int t = tid; t < NT; t += 256) {
        float e = expf(at[t] - m);
        at[t] = e;
        l += e;
    }
    red[tid] = l; __syncthreads();
    for (int o = 128; o; o >>= 1) {
        if (tid < o) red[tid] += red[tid + o];
        __syncthreads();
    }
    float inv = 1.f / red[0];
    __syncthreads();

    if (tid < NH) {
        const float* e = enc + (size_t)b * NT * NH + tid;
        float a = 0.f;
        #pragma unroll 8
        for (int t = 0; t < NT; t++) a = fmaf(at[t], e[(size_t)t * NH], a);
        g_context[b * NH + tid] = a * inv;
    }
}

// ============================================================================
// K4: 5-step decode. context/h_pre/c0 are step-constant; only scalar x feeds
// back. gates_const = b_ih + h_pre + context @ W_ih[:,1:].T  (computed once).
// ============================================================================
__global__ void k_decode(const float* __restrict__ x_in, const float* __restrict__ c0,
                         const float* __restrict__ Wih, const float* __restrict__ bih,
                         const float* __restrict__ W1, const float* __restrict__ b1,
                         const float* __restrict__ W2, const float* __restrict__ b2,
                         const float* __restrict__ W3, const float* __restrict__ b3,
                         float* __restrict__ out) {
    int b = blockIdx.x, tid = threadIdx.x;
    __shared__ float ctx[NH], c0s[NH], gc[NH4], w0[NH4];
    __shared__ float buf0[NH], buf1[100], buf2[56];
    __shared__ float xcur;

    if (tid < NH) {
        ctx[tid] = g_context[b * NH + tid];
        c0s[tid] = c0[b * NH + tid];
    }
    __syncthreads();

    for (int j = tid; j < NH4; j += 256) {
        float s = bih[j] + g_hpre[b * NH4 + j];
        const float* w = Wih + (size_t)j * (NH + 1);
        w0[j] = w[0];
        #pragma unroll 4
        for (int h = 0; h < NH; h++) s = fmaf(ctx[h], w[1 + h], s);
        gc[j] = s;
    }
    if (tid == 0) xcur = x_in[b];
    __syncthreads();

    for (int st = 0; st < NSTEP; st++) {
        float xv = xcur;
        if (tid < NH) {
            float gi = gc[tid]          + xv * w0[tid];
            float gf = gc[NH + tid]     + xv * w0[NH + tid];
            float gg = gc[2 * NH + tid] + xv * w0[2 * NH + tid];
            float go = gc[3 * NH + tid] + xv * w0[3 * NH + tid];
            float c  = sigm(gf) * c0s[tid] + sigm(gi) * tanhf(gg);
            float hn = sigm(go) * tanhf(c);
            buf0[tid] = fmaxf(hn, 0.f);
        }
        __syncthreads();
        if (tid < 100) {
            float s = b1[tid];
            const float* w = W1 + tid * NH;
            #pragma unroll 4
            for (int h = 0; h < NH; h++) s = fmaf(w[h], buf0[h], s);
            buf1[tid] = fmaxf(s, 0.f);
        }
        __syncthreads();
        if (tid < 50) {
            float s = b2[tid];
            const float* w = W2 + tid * 100;
            #pragma unroll 4
            for (int h = 0; h < 100; h++) s = fmaf(w[h], buf1[h], s);
            buf2[tid] = fmaxf(s, 0.f);
        }
        __syncthreads();
        if (tid == 0) {
            float s = b3[0];
            #pragma unroll
            for (int j = 0; j < 50; j++) s = fmaf(W3[j], buf2[j], s);
            out[b * NSTEP + st] = s;
            xcur = s;  // decoded output feeds back as next input
        }
        __syncthreads();
    }
}

// ============================================================================
extern "C" void kernel_launch(void* const* d_in, const int* in_sizes, int n_in,
                              void* d_out, int out_size) {
    const float* x   = (const float*)d_in[0];
    const float* h0  = (const float*)d_in[1];
    const float* c0  = (const float*)d_in[2];
    const float* enc = (const float*)d_in[3];
    const float* Wa  = (const float*)d_in[4];
    const float* ba  = (const float*)d_in[5];
    const float* Ua  = (const float*)d_in[6];
    const float* bua = (const float*)d_in[7];
    const float* Va  = (const float*)d_in[8];
    const float* bva = (const float*)d_in[9];
    const float* Wih = (const float*)d_in[10];
    const float* Whh = (const float*)d_in[11];
    const float* bih = (const float*)d_in[12];
    const float* bhh = (const float*)d_in[13];
    const float* W1  = (const float*)d_in[14];
    const float* b1  = (const float*)d_in[15];
    const float* W2  = (const float*)d_in[16];
    const float* b2  = (const float*)d_in[17];
    const float* W3  = (const float*)d_in[18];
    const float* b3  = (const float*)d_in[19];
    float* out = (float*)d_out;

    cudaFuncSetAttribute(k_scores, cudaFuncAttributeMaxDynamicSharedMemorySize,
                         (int)SMEM_SCORES);

    k_pre<<<NB, 256>>>(h0, Wa, ba, Whh, bhh);
    k_scores<<<dim3(NT / MT, NB), 256, SMEM_SCORES>>>(enc, Ua, bua, Va, bva);
    k_softctx<<<NB, 256>>>(enc);
    k_decode<<<NB, 256>>>(x, c0, Wih, bih, W1, b1, W2, b2, W3, b3, out);
}

// round 2
// speedup vs baseline: 2.4564x; 2.4564x over previous
#include <cuda_runtime.h>
#include <cuda_bf16.h>
#include <math.h>
#include <stdint.h>

#define NB 128
#define NT 2048
#define NH 200
#define NH4 800
#define NSTEP 5

// ---- scratch ----
__device__ float g_qproj[NB * NH];
__device__ float g_hpre[NB * NH4];
__device__ float g_scores[NB * NT];
__device__ float g_context[NB * NH];
__device__ float g_gc[NB * NH4];

__device__ __forceinline__ float sigm(float x) { return 1.f / (1.f + expf(-x)); }

// FMA-only tanh: Pade(7,6) + bit-hack Newton reciprocal. No MUFU.
// Max abs err ~4.6e-4 (clamp at 4.2).
__device__ __forceinline__ float tanh_fma(float x) {
    x = fminf(fmaxf(x, -4.2f), 4.2f);
    float s = x * x;
    float p = s + 378.f;
    p = fmaf(p, s, 17325.f);
    p = fmaf(p, s, 135135.f);           // P(s)
    float q = fmaf(28.f, s, 3150.f);
    q = fmaf(q, s, 62370.f);
    q = fmaf(q, s, 135135.f);           // Q(s) >= 135135 > 0
    float r = __int_as_float(0x7EF311C3 - __float_as_int(q));
    r = r * fmaf(-q, r, 2.f);
    r = r * fmaf(-q, r, 2.f);
    return (x * p) * r;
}

__device__ __forceinline__ uint32_t pack_bf2(float lo, float hi) {
    uint32_t r;
    asm("cvt.rn.bf16x2.f32 %0, %1, %2;" : "=r"(r) : "f"(hi), "f"(lo));
    return r;
}

__device__ __forceinline__ float warp_sum(float s) {
    #pragma unroll
    for (int o = 16; o; o >>= 1) s += __shfl_xor_sync(0xffffffffu, s, o);
    return s;
}

// ============================================================================
// K1: warp-per-output gemv: q_proj (Wa) + h_pre (W_hh).  grid(5, NB)
// ============================================================================
__global__ void k_pre(const float* __restrict__ h0, const float* __restrict__ Wa,
                      const float* __restrict__ ba, const float* __restrict__ Whh,
                      const float* __restrict__ bhh) {
    const int b = blockIdx.y, oc = blockIdx.x, tid = threadIdx.x;
    const int w = tid >> 5, l = tid & 31;
    __shared__ float hs[NH];
    if (tid < NH) hs[tid] = h0[b * NH + tid];
    __syncthreads();
    #pragma unroll 1
    for (int i = 0; i < 25; i++) {
        int o = oc * 200 + w * 25 + i;
        const float* row;
        if (o < NH) row = Wa + o * NH;
        else        row = Whh + (o - NH) * NH;
        float s = 0.f;
        #pragma unroll
        for (int k = l; k < NH; k += 32) s = fmaf(hs[k], row[k], s);
        s = warp_sum(s);
        if (l == 0) {
            if (o < NH) g_qproj[b * NH + o] = s + ba[o];
            else        g_hpre[b * NH4 + (o - NH)] = s + bhh[o - NH];
        }
    }
}

// ============================================================================
// K2: scores via bf16 mma.sync m16n8k16, fused tanh+Va epilogue (FMA tanh)
// CTA: 128 tokens x 208 cols x 208 K.  512 threads = 16 warps (8m x 2n).
// ============================================================================
#define ASTR 216            // bf16 row stride (432B: conflict-free ldmatrix)
#define SM_AS_BYTES (128 * ASTR * 2)          // 55296
#define SM_BS_BYTES (208 * ASTR * 2)          // 89856
#define SMEM_SCORES (SM_AS_BYTES + SM_BS_BYTES + (208 + 208 + 128) * 4)

__global__ __launch_bounds__(512, 1) void k_scores(
    const float* __restrict__ enc, const float* __restrict__ Ua,
    const float* __restrict__ bua, const float* __restrict__ Va,
    const float* __restrict__ bva) {
    extern __shared__ char smc[];
    uint32_t* As32 = (uint32_t*)smc;                          // [128][108] bf16x2
    uint32_t* Bs32 = (uint32_t*)(smc + SM_AS_BYTES);          // [208][108]
    float* qb   = (float*)(smc + SM_AS_BYTES + SM_BS_BYTES);  // [208]
    float* va   = qb + 208;
    float* srow = va + 208;                                   // [128]

    const int b = blockIdx.y, tile = blockIdx.x, tid = threadIdx.x;
    const int t0 = tile * 128;
    const float* eb = enc + ((size_t)b * NT + t0) * NH;

    // ---- stage tiles (fp32 -> bf16) ----
    for (int i = tid; i < 128 * 108; i += 512) {
        int m = i / 108, p = i % 108;
        uint32_t v = 0;
        if (p < 100) { float2 f = *(const float2*)(eb + m * NH + 2 * p); v = pack_bf2(f.x, f.y); }
        As32[m * 108 + p] = v;
    }
    for (int i = tid; i < 208 * 108; i += 512) {
        int n = i / 108, p = i % 108;
        uint32_t v = 0;
        if (n < NH && p < 100) { float2 f = *(const float2*)(Ua + n * NH + 2 * p); v = pack_bf2(f.x, f.y); }
        Bs32[n * 108 + p] = v;
    }
    for (int j = tid; j < 208; j += 512) {
        qb[j] = (j < NH) ? (g_qproj[b * NH + j] + bua[j]) : 0.f;
        va[j] = (j < NH) ? Va[j] : 0.f;
    }
    if (tid < 128) srow[tid] = 0.f;
    __syncthreads();

    const int l = tid & 31, wid = tid >> 5;
    const int mw = wid & 7, nw = wid >> 3;   // 8 m-warps x 2 n-warps

    // ---- A fragments, all 13 k-tiles, hoisted ----
    uint32_t a[13][4];
    {
        uint32_t abase = (uint32_t)__cvta_generic_to_shared(As32)
                       + ((mw * 16 + (l & 15)) * ASTR + ((l >> 4) * 8)) * 2;
        #pragma unroll
        for (int kt = 0; kt < 13; kt++) {
            asm volatile("ldmatrix.sync.aligned.m8n8.x4.shared.b16 {%0,%1,%2,%3}, [%4];"
                : "=r"(a[kt][0]), "=r"(a[kt][1]), "=r"(a[kt][2]), "=r"(a[kt][3])
                : "r"(abase + kt * 32));
        }
    }

    float slo = 0.f, shi = 0.f;
    const uint32_t bbase = (uint32_t)__cvta_generic_to_shared(Bs32)
                         + ((nw * 104 + (l & 7)) * ASTR + (((l >> 3) & 1) * 8)) * 2;
    #pragma unroll 1
    for (int jt = 0; jt < 13; jt++) {
        float c0 = 0.f, c1 = 0.f, c2 = 0.f, c3 = 0.f;
        uint32_t bb = bbase + jt * 8 * ASTR * 2;
        #pragma unroll
        for (int kt = 0; kt < 13; kt++) {
            uint32_t b0, b1;
            asm volatile("ldmatrix.sync.aligned.m8n8.x2.shared.b16 {%0,%1}, [%2];"
                : "=r"(b0), "=r"(b1) : "r"(bb + kt * 32));
            asm volatile("mma.sync.aligned.m16n8k16.row.col.f32.bf16.bf16.f32 "
                "{%0,%1,%2,%3},{%4,%5,%6,%7},{%8,%9},{%0,%1,%2,%3};"
                : "+f"(c0), "+f"(c1), "+f"(c2), "+f"(c3)
                : "r"(a[kt][0]), "r"(a[kt][1]), "r"(a[kt][2]), "r"(a[kt][3]),
                  "r"(b0), "r"(b1));
        }
        const int j0 = nw * 104 + jt * 8 + 2 * (l & 3);
        const float2 vv = *(const float2*)&va[j0];
        const float2 qq = *(const float2*)&qb[j0];
        slo = fmaf(vv.x, tanh_fma(c0 + qq.x), slo);
        slo = fmaf(vv.y, tanh_fma(c1 + qq.y), slo);
        shi = fmaf(vv.x, tanh_fma(c2 + qq.x), shi);
        shi = fmaf(vv.y, tanh_fma(c3 + qq.y), shi);
    }
    slo += __shfl_xor_sync(0xffffffffu, slo, 1);
    slo += __shfl_xor_sync(0xffffffffu, slo, 2);
    shi += __shfl_xor_sync(0xffffffffu, shi, 1);
    shi += __shfl_xor_sync(0xffffffffu, shi, 2);
    if ((l & 3) == 0) {
        atomicAdd(&srow[mw * 16 + (l >> 2)], slo);
        atomicAdd(&srow[mw * 16 + (l >> 2) + 8], shi);
    }
    __syncthreads();
    if (tid < 128) g_scores[(size_t)b * NT + t0 + tid] = srow[tid] + bva[0];
}

// ============================================================================
// K3: softmax over T + context.  512 threads, 2-way t-split for context.
// ============================================================================
__global__ __launch_bounds__(512) void k_softctx(const float* __restrict__ enc) {
    const int b = blockIdx.x, tid = threadIdx.x;
    __shared__ float at[NT];
    __shared__ float red[512];
    __shared__ float part[2][NH];

    float m = -1e30f;
    for (int t = tid; t < NT; t += 512) {
        float s = g_scores[(size_t)b * NT + t];
        at[t] = s;
        m = fmaxf(m, s);
    }
    red[tid] = m; __syncthreads();
    for (int o = 256; o; o >>= 1) {
        if (tid < o) red[tid] = fmaxf(red[tid], red[tid + o]);
        __syncthreads();
    }
    m = red[0]; __syncthreads();

    float lsum = 0.f;
    for (int t = tid; t < NT; t += 512) {
        float e = expf(at[t] - m);
        at[t] = e;
        lsum += e;
    }
    red[tid] = lsum; __syncthreads();
    for (int o = 256; o; o >>= 1) {
        if (tid < o) red[tid] += red[tid + o];
        __syncthreads();
    }
    const float inv = 1.f / red[0];
    __syncthreads();

    const int half = tid >> 8, hh = tid & 255;
    if (hh < NH) {
        const float* e = enc + (size_t)b * NT * NH + (size_t)half * 1024 * NH + hh;
        const float* atp = at + half * 1024;
        float a = 0.f;
        #pragma unroll 8
        for (int t = 0; t < 1024; t++) a = fmaf(atp[t], e[(size_t)t * NH], a);
        part[half][hh] = a;
    }
    __syncthreads();
    if (tid < NH) g_context[b * NH + tid] = (part[0][tid] + part[1][tid]) * inv;
}

// ============================================================================
// K4: gates_const[b,j] = b_ih[j] + h_pre[b,j] + ctx . W_ih[j,1:]   grid(4,NB)
// ============================================================================
__global__ void k_gates(const float* __restrict__ Wih, const float* __restrict__ bih) {
    const int b = blockIdx.y, jc = blockIdx.x, tid = threadIdx.x;
    const int w = tid >> 5, l = tid & 31;
    __shared__ float ctx[NH];
    if (tid < NH) ctx[tid] = g_context[b * NH + tid];
    __syncthreads();
    #pragma unroll 1
    for (int i = 0; i < 25; i++) {
        int j = jc * 200 + w * 25 + i;
        const float* row = Wih + (size_t)j * (NH + 1) + 1;
        float s = 0.f;
        #pragma unroll
        for (int k = l; k < NH; k += 32) s = fmaf(ctx[k], row[k], s);
        s = warp_sum(s);
        if (l == 0) g_gc[b * NH4 + j] = s + bih[j] + g_hpre[b * NH4 + j];
    }
}

// ============================================================================
// K5: 5-step decode.  Weights staged in smem; warp-per-output MLP layers.
// ============================================================================
#define SMEM_DEC ((20000 + 5000 + 64 + 128 + 64 + NH4 + NH4 + NH + NH + 128 + 64 + 8) * 4)
__global__ __launch_bounds__(256) void k_decode(
    const float* __restrict__ x_in, const float* __restrict__ c0,
    const float* __restrict__ Wih,
    const float* __restrict__ W1, const float* __restrict__ b1,
    const float* __restrict__ W2, const float* __restrict__ b2,
    const float* __restrict__ W3, const float* __restrict__ b3,
    float* __restrict__ out) {
    extern __shared__ float sd[];
    float* W1s = sd;              // 20000
    float* W2s = W1s + 20000;     // 5000
    float* W3s = W2s + 5000;      // 64
    float* b1s = W3s + 64;        // 128
    float* b2s = b1s + 128;       // 64
    float* gc  = b2s + 64;        // 800
    float* w0  = gc + NH4;        // 800
    float* c0s = w0 + NH4;        // 200
    float* buf0 = c0s + NH;       // 200
    float* buf1 = buf0 + NH;      // 128
    float* buf2 = buf1 + 128;     // 64
    float* xcur = buf2 + 64;      // 1

    const int b = blockIdx.x, tid = threadIdx.x;
    const int w = tid >> 5, l = tid & 31;

    for (int i = tid; i < 20000; i += 256) W1s[i] = W1[i];
    for (int i = tid; i < 5000; i += 256) W2s[i] = W2[i];
    if (tid < 50) { W3s[tid] = W3[tid]; b2s[tid] = b2[tid]; }
    if (tid < 100) b1s[tid] = b1[tid];
    for (int i = tid; i < NH4; i += 256) {
        gc[i] = g_gc[b * NH4 + i];
        w0[i] = Wih[(size_t)i * (NH + 1)];
    }
    if (tid < NH) c0s[tid] = c0[b * NH + tid];
    if (tid == 0) xcur[0] = x_in[b];
    __syncthreads();

    const float b3v = b3[0];
    for (int st = 0; st < NSTEP; st++) {
        const float xv = xcur[0];
        if (tid < NH) {
            float gi = fmaf(xv, w0[tid], gc[tid]);
            float gf = fmaf(xv, w0[NH + tid], gc[NH + tid]);
            float gg = fmaf(xv, w0[2 * NH + tid], gc[2 * NH + tid]);
            float go = fmaf(xv, w0[3 * NH + tid], gc[3 * NH + tid]);
            float c  = sigm(gf) * c0s[tid] + sigm(gi) * tanhf(gg);
            buf0[tid] = fmaxf(sigm(go) * tanhf(c), 0.f);
        }
        __syncthreads();
        // L1: 100 x 200
        #pragma unroll 1
        for (int i = 0; i < 13; i++) {
            int j = w + 8 * i; int jj = min(j, 99);
            float s = 0.f;
            #pragma unroll
            for (int k = l; k < NH; k += 32) s = fmaf(W1s[jj * NH + k], buf0[k], s);
            s = warp_sum(s);
            if (l == 0 && j < 100) buf1[j] = fmaxf(s + b1s[j], 0.f);
        }
        __syncthreads();
        // L2: 50 x 100
        #pragma unroll 1
        for (int i = 0; i < 7; i++) {
            int j = w + 8 * i; int jj = min(j, 49);
            float s = 0.f;
            #pragma unroll
            for (int k = l; k < 100; k += 32) s = fmaf(W2s[jj * 100 + k], buf1[k], s);
            s = warp_sum(s);
            if (l == 0 && j < 50) buf2[j] = fmaxf(s + b2s[j], 0.f);
        }
        __syncthreads();
        // L3: 1 x 50
        if (w == 0) {
            float s = (l < 50) ? W3s[l] * buf2[l] : 0.f;
            if (l < 18) s = fmaf(W3s[l + 32], buf2[l + 32], s);
            s = warp_sum(s);
            if (l == 0) {
                float y = s + b3v;
                out[b * NSTEP + st] = y;
                xcur[0] = y;
            }
        }
        __syncthreads();
    }
}

// ============================================================================
extern "C" void kernel_launch(void* const* d_in, const int* in_sizes, int n_in,
                              void* d_out, int out_size) {
    const float* x   = (const float*)d_in[0];
    const float* h0  = (const float*)d_in[1];
    const float* c0  = (const float*)d_in[2];
    const float* enc = (const float*)d_in[3];
    const float* Wa  = (const float*)d_in[4];
    const float* ba  = (const float*)d_in[5];
    const float* Ua  = (const float*)d_in[6];
    const float* bua = (const float*)d_in[7];
    const float* Va  = (const float*)d_in[8];
    const float* bva = (const float*)d_in[9];
    const float* Wih = (const float*)d_in[10];
    const float* Whh = (const float*)d_in[11];
    const float* bih = (const float*)d_in[12];
    const float* bhh = (const float*)d_in[13];
    const float* W1  = (const float*)d_in[14];
    const float* b1  = (const float*)d_in[15];
    const float* W2  = (const float*)d_in[16];
    const float* b2  = (const float*)d_in[17];
    const float* W3  = (const float*)d_in[18];
    const float* b3  = (const float*)d_in[19];
    float* out = (float*)d_out;

    cudaFuncSetAttribute(k_scores, cudaFuncAttributeMaxDynamicSharedMemorySize,
                         (int)SMEM_SCORES);
    cudaFuncSetAttribute(k_decode, cudaFuncAttributeMaxDynamicSharedMemorySize,
                         (int)SMEM_DEC);

    k_pre<<<dim3(5, NB), 256>>>(h0, Wa, ba, Whh, bhh);
    k_scores<<<dim3(NT / 128, NB), 512, SMEM_SCORES>>>(enc, Ua, bua, Va, bva);
    k_softctx<<<NB, 512>>>(enc);
    k_gates<<<dim3(4, NB), 256>>>(Wih, bih);
    k_decode<<<NB, 256, SMEM_DEC>>>(x, c0, Wih, W1, b1, W2, b2, W3, b3, out);
}

// round 4
// speedup vs baseline: 2.6539x; 1.0804x over previous
#include <cuda_runtime.h>
#include <cuda_bf16.h>
#include <math.h>
#include <stdint.h>

#define NB 128
#define NT 2048
#define NH 200
#define NH4 800
#define NSTEP 5

// ---- scratch ----
__device__ float g_qproj[NB * NH];
__device__ float g_hpre[NB * NH4];
__device__ float g_scores[NB * NT];
__device__ float g_context[NB * NH];
__device__ float g_gc[NB * NH4];

__device__ __forceinline__ float sigm(float x) { return 1.f / (1.f + expf(-x)); }

// MUFU tanh: t = 1 - 2/(1 + e^{2x}).  Exact at +/-inf, ~1e-6 rel err.
__device__ __forceinline__ float tanh_mufu(float x) {
    float m = x * 2.8853900817779268f;   // 2*log2(e)
    float e; asm("ex2.approx.ftz.f32 %0, %1;" : "=f"(e) : "f"(m));
    float d = 1.f + e;
    float rc; asm("rcp.approx.ftz.f32 %0, %1;" : "=f"(rc) : "f"(d));
    return fmaf(-2.f, rc, 1.f);
}

__device__ __forceinline__ uint32_t pack_bf2(float lo, float hi) {
    uint32_t r;
    asm("cvt.rn.bf16x2.f32 %0, %1, %2;" : "=r"(r) : "f"(hi), "f"(lo));
    return r;
}
__device__ __forceinline__ float warp_sum(float s) {
    #pragma unroll
    for (int o = 16; o; o >>= 1) s += __shfl_xor_sync(0xffffffffu, s, o);
    return s;
}
__device__ __forceinline__ uint32_t s2u(const void* p) {
    return (uint32_t)__cvta_generic_to_shared(p);
}

// ============================================================================
// K1: warp-per-output gemv: q_proj (Wa) + h_pre (W_hh).  grid(5, NB)
// ============================================================================
__global__ void k_pre(const float* __restrict__ h0, const float* __restrict__ Wa,
                      const float* __restrict__ ba, const float* __restrict__ Whh,
                      const float* __restrict__ bhh) {
    const int b = blockIdx.y, oc = blockIdx.x, tid = threadIdx.x;
    const int w = tid >> 5, l = tid & 31;
    __shared__ float hs[NH];
    if (tid < NH) hs[tid] = h0[b * NH + tid];
    __syncthreads();
    #pragma unroll 1
    for (int i = 0; i < 25; i++) {
        int o = oc * 200 + w * 25 + i;
        const float* row;
        if (o < NH) row = Wa + o * NH;
        else        row = Whh + (o - NH) * NH;
        float s = 0.f;
        #pragma unroll
        for (int k = l; k < NH; k += 32) s = fmaf(hs[k], row[k], s);
        s = warp_sum(s);
        if (l == 0) {
            if (o < NH) g_qproj[b * NH + o] = s + ba[o];
            else        g_hpre[b * NH4 + (o - NH)] = s + bhh[o - NH];
        }
    }
}

// ============================================================================
// K2: scores via bf16 mma.sync m16n8k16.  PERSISTENT 148 CTAs, 512 threads.
//   B = Ua (224x208 bf16, padded) staged ONCE per CTA.
//   A = enc tile (64 tokens x 208) double-buffered; staging of tile i+1
//       overlaps the mma loop of tile i (A-frags pulled to regs first).
//   Epilogue: MUFU tanh + Va dot, atomic-free 4-slab reduction.
//   16 warps = 4 m-warps (64 rows) x 4 n-warps (56 cols each).
// ============================================================================
#define NCTA 148
#define MT 64
#define NP 224
#define ASTR 216                  // bf16 per smem row (432 B, 16B-aligned)
#define AW 108                    // uint32 (bf16x2) per row
#define BS_U32 (NP * AW)          // 24192 u32 = 96768 B
#define AS_U32 (MT * AW)          // 6912 u32  = 27648 B
#define NTILES (NB * 32)          // 4096 tiles of 64 tokens
#define SMEM_SC ((BS_U32 + 2 * AS_U32) * 4 + 2 * NP * 8 + 4 * 64 * 4 + 16)

__device__ __forceinline__ void stage_tile(
    uint32_t* __restrict__ dst, float2* __restrict__ vqd,
    const float* __restrict__ enc, const float* __restrict__ Va,
    const float* __restrict__ bua, int b, int trow, int tid) {
    const float* eb = enc + ((size_t)b * NT + trow) * NH;
    #pragma unroll 1
    for (int i = tid; i < MT * AW; i += 512) {
        int r = i / AW, p = i - r * AW;
        uint32_t v = 0;
        if (p < 100) {
            float2 f = *(const float2*)(eb + r * NH + 2 * p);
            v = pack_bf2(f.x, f.y);
        }
        dst[r * AW + p] = v;
    }
    if (tid < NP) {
        float vv = 0.f, qq = 0.f;
        if (tid < NH) { vv = Va[tid]; qq = g_qproj[b * NH + tid] + bua[tid]; }
        vqd[tid] = make_float2(vv, qq);
    }
}

__global__ __launch_bounds__(512, 1) void k_scores(
    const float* __restrict__ enc, const float* __restrict__ Ua,
    const float* __restrict__ bua, const float* __restrict__ Va,
    const float* __restrict__ bva) {
    extern __shared__ uint32_t sm32[];
    uint32_t* Bs  = sm32;
    uint32_t* As0 = Bs + BS_U32;
    uint32_t* As1 = As0 + AS_U32;
    float2*   vq  = (float2*)(As1 + AS_U32);     // [2][NP]
    float*    srow = (float*)(vq + 2 * NP);      // [4][64]

    const int tid = threadIdx.x, l = tid & 31, wid = tid >> 5;
    const int mw = wid & 3, nw = wid >> 2;
    const int bid = blockIdx.x;
    const float bv0 = bva[0];

    // ---- zero B (covers n/k padding), then fill Ua as bf16 ----
    for (int i = tid; i < BS_U32; i += 512) Bs[i] = 0;
    __syncthreads();
    for (int i = tid; i < NH * 100; i += 512) {
        int n = i / 100, k2 = i - n * 100;
        float2 f = *(const float2*)(Ua + n * NH + 2 * k2);
        Bs[n * AW + k2] = pack_bf2(f.x, f.y);
    }

    const int ntile = (NTILES - bid + NCTA - 1) / NCTA;
    // ---- prologue: stage tile 0 ----
    {
        int gt = bid;
        stage_tile(As0, vq, enc, Va, bua, gt >> 5, (gt & 31) << 6, tid);
    }
    __syncthreads();

    const uint32_t bbase = s2u(Bs) + ((nw * 56 + (l & 7)) * ASTR + ((l >> 3) & 1) * 8) * 2;

    #pragma unroll 1
    for (int it = 0; it < ntile; it++) {
        const int cur = it & 1;
        uint32_t* Ac = cur ? As1 : As0;

        // pull all A fragments to registers (frees the buffer logically)
        uint32_t a[13][4];
        {
            uint32_t abase = s2u(Ac) + ((mw * 16 + (l & 15)) * ASTR + (l >> 4) * 8) * 2;
            #pragma unroll
            for (int kt = 0; kt < 13; kt++)
                asm volatile("ldmatrix.sync.aligned.m8n8.x4.shared.b16 {%0,%1,%2,%3}, [%4];"
                    : "=r"(a[kt][0]), "=r"(a[kt][1]), "=r"(a[kt][2]), "=r"(a[kt][3])
                    : "r"(abase + kt * 32));
        }

        // stage next tile into the other buffer (overlaps mma below)
        if (it + 1 < ntile) {
            int gtn = bid + (it + 1) * NCTA;
            stage_tile(cur ? As0 : As1, vq + (1 - cur) * NP,
                       enc, Va, bua, gtn >> 5, (gtn & 31) << 6, tid);
        }

        // ---- mma + fused tanh/Va epilogue ----
        float slo = 0.f, shi = 0.f;
        const float2* vql = vq + cur * NP;
        #pragma unroll 1
        for (int jt = 0; jt < 7; jt++) {
            float c0 = 0.f, c1 = 0.f, c2 = 0.f, c3 = 0.f;
            uint32_t bb = bbase + jt * 8 * ASTR * 2;
            #pragma unroll
            for (int kt = 0; kt < 13; kt++) {
                uint32_t b0, b1;
                asm volatile("ldmatrix.sync.aligned.m8n8.x2.shared.b16 {%0,%1}, [%2];"
                    : "=r"(b0), "=r"(b1) : "r"(bb + kt * 32));
                asm volatile("mma.sync.aligned.m16n8k16.row.col.f32.bf16.bf16.f32 "
                    "{%0,%1,%2,%3},{%4,%5,%6,%7},{%8,%9},{%0,%1,%2,%3};"
                    : "+f"(c0), "+f"(c1), "+f"(c2), "+f"(c3)
                    : "r"(a[kt][0]), "r"(a[kt][1]), "r"(a[kt][2]), "r"(a[kt][3]),
                      "r"(b0), "r"(b1));
            }
            const int j0 = nw * 56 + jt * 8 + 2 * (l & 3);
            const float2 v0 = vql[j0], v1 = vql[j0 + 1];
            slo = fmaf(v0.x, tanh_mufu(c0 + v0.y), slo);
            slo = fmaf(v1.x, tanh_mufu(c1 + v1.y), slo);
            shi = fmaf(v0.x, tanh_mufu(c2 + v0.y), shi);
            shi = fmaf(v1.x, tanh_mufu(c3 + v1.y), shi);
        }
        slo += __shfl_xor_sync(0xffffffffu, slo, 1);
        slo += __shfl_xor_sync(0xffffffffu, slo, 2);
        shi += __shfl_xor_sync(0xffffffffu, shi, 1);
        shi += __shfl_xor_sync(0xffffffffu, shi, 2);
        if ((l & 3) == 0) {
            srow[nw * 64 + mw * 16 + (l >> 2)] = slo;
            srow[nw * 64 + mw * 16 + (l >> 2) + 8] = shi;
        }
        __syncthreads();   // staging + srow slabs complete

        const int gt = bid + it * NCTA;
        if (tid < 64) {
            g_scores[(size_t)(gt >> 5) * NT + ((gt & 31) << 6) + tid] =
                srow[tid] + srow[64 + tid] + srow[128 + tid] + srow[192 + tid] + bv0;
        }
        __syncthreads();   // srow consumed before next tile overwrites
    }
}

// ============================================================================
// K3: softmax over T + context.  1024 threads, 4-way token split.
// ============================================================================
__global__ __launch_bounds__(1024) void k_softctx(const float* __restrict__ enc) {
    const int b = blockIdx.x, tid = threadIdx.x;
    __shared__ float at[NT];
    __shared__ float red[1024];
    __shared__ float part[4][NH];

    float m = -1e30f;
    #pragma unroll
    for (int t = tid; t < NT; t += 1024) {
        float s = g_scores[(size_t)b * NT + t];
        at[t] = s;
        m = fmaxf(m, s);
    }
    red[tid] = m; __syncthreads();
    for (int o = 512; o; o >>= 1) {
        if (tid < o) red[tid] = fmaxf(red[tid], red[tid + o]);
        __syncthreads();
    }
    m = red[0]; __syncthreads();

    float lsum = 0.f;
    #pragma unroll
    for (int t = tid; t < NT; t += 1024) {
        float e = expf(at[t] - m);
        at[t] = e;
        lsum += e;
    }
    red[tid] = lsum; __syncthreads();
    for (int o = 512; o; o >>= 1) {
        if (tid < o) red[tid] += red[tid + o];
        __syncthreads();
    }
    const float inv = 1.f / red[0];
    __syncthreads();

    const int p = tid >> 8, hh = tid & 255;
    if (hh < NH) {
        const float* e = enc + (size_t)b * NT * NH + (size_t)p * 512 * NH + hh;
        const float* atp = at + p * 512;
        float a = 0.f;
        #pragma unroll 8
        for (int t = 0; t < 512; t++) a = fmaf(atp[t], e[(size_t)t * NH], a);
        part[p][hh] = a;
    }
    __syncthreads();
    if (tid < NH)
        g_context[b * NH + tid] =
            (part[0][tid] + part[1][tid] + part[2][tid] + part[3][tid]) * inv;
}

// ============================================================================
// K4: gates_const[b,j] = b_ih[j] + h_pre[b,j] + ctx . W_ih[j,1:]   grid(4,NB)
// ============================================================================
__global__ void k_gates(const float* __restrict__ Wih, const float* __restrict__ bih) {
    const int b = blockIdx.y, jc = blockIdx.x, tid = threadIdx.x;
    const int w = tid >> 5, l = tid & 31;
    __shared__ float ctx[NH];
    if (tid < NH) ctx[tid] = g_context[b * NH + tid];
    __syncthreads();
    #pragma unroll 1
    for (int i = 0; i < 25; i++) {
        int j = jc * 200 + w * 25 + i;
        const float* row = Wih + (size_t)j * (NH + 1) + 1;
        float s = 0.f;
        #pragma unroll
        for (int k = l; k < NH; k += 32) s = fmaf(ctx[k], row[k], s);
        s = warp_sum(s);
        if (l == 0) g_gc[b * NH4 + j] = s + bih[j] + g_hpre[b * NH4 + j];
    }
}

// ============================================================================
// K5: 5-step decode.
// ============================================================================
#define SMEM_DEC ((20000 + 5000 + 64 + 128 + 64 + NH4 + NH4 + NH + NH + 128 + 64 + 8) * 4)
__global__ __launch_bounds__(256) void k_decode(
    const float* __restrict__ x_in, const float* __restrict__ c0,
    const float* __restrict__ Wih,
    const float* __restrict__ W1, const float* __restrict__ b1,
    const float* __restrict__ W2, const float* __restrict__ b2,
    const float* __restrict__ W3, const float* __restrict__ b3,
    float* __restrict__ out) {
    extern __shared__ float sd[];
    float* W1s = sd;
    float* W2s = W1s + 20000;
    float* W3s = W2s + 5000;
    float* b1s = W3s + 64;
    float* b2s = b1s + 128;
    float* gc  = b2s + 64;
    float* w0  = gc + NH4;
    float* c0s = w0 + NH4;
    float* buf0 = c0s + NH;
    float* buf1 = buf0 + NH;
    float* buf2 = buf1 + 128;
    float* xcur = buf2 + 64;

    const int b = blockIdx.x, tid = threadIdx.x;
    const int w = tid >> 5, l = tid & 31;

    for (int i = tid; i < 20000; i += 256) W1s[i] = W1[i];
    for (int i = tid; i < 5000; i += 256) W2s[i] = W2[i];
    if (tid < 50) { W3s[tid] = W3[tid]; b2s[tid] = b2[tid]; }
    if (tid < 100) b1s[tid] = b1[tid];
    for (int i = tid; i < NH4; i += 256) {
        gc[i] = g_gc[b * NH4 + i];
        w0[i] = Wih[(size_t)i * (NH + 1)];
    }
    if (tid < NH) c0s[tid] = c0[b * NH + tid];
    if (tid == 0) xcur[0] = x_in[b];
    __syncthreads();

    const float b3v = b3[0];
    for (int st = 0; st < NSTEP; st++) {
        const float xv = xcur[0];
        if (tid < NH) {
            float gi = fmaf(xv, w0[tid], gc[tid]);
            float gf = fmaf(xv, w0[NH + tid], gc[NH + tid]);
            float gg = fmaf(xv, w0[2 * NH + tid], gc[2 * NH + tid]);
            float go = fmaf(xv, w0[3 * NH + tid], gc[3 * NH + tid]);
            float c  = sigm(gf) * c0s[tid] + sigm(gi) * tanhf(gg);
            buf0[tid] = fmaxf(sigm(go) * tanhf(c), 0.f);
        }
        __syncthreads();
        #pragma unroll 1
        for (int i = 0; i < 13; i++) {
            int j = w + 8 * i; int jj = min(j, 99);
            float s = 0.f;
            #pragma unroll
            for (int k = l; k < NH; k += 32) s = fmaf(W1s[jj * NH + k], buf0[k], s);
            s = warp_sum(s);
            if (l == 0 && j < 100) buf1[j] = fmaxf(s + b1s[j], 0.f);
        }
        __syncthreads();
        #pragma unroll 1
        for (int i = 0; i < 7; i++) {
            int j = w + 8 * i; int jj = min(j, 49);
            float s = 0.f;
            #pragma unroll
            for (int k = l; k < 100; k += 32) s = fmaf(W2s[jj * 100 + k], buf1[k], s);
            s = warp_sum(s);
            if (l == 0 && j < 50) buf2[j] = fmaxf(s + b2s[j], 0.f);
        }
        __syncthreads();
        if (w == 0) {
            float s = (l < 50) ? W3s[l] * buf2[l] : 0.f;
            if (l < 18) s = fmaf(W3s[l + 32], buf2[l + 32], s);
            s = warp_sum(s);
            if (l == 0) {
                float y = s + b3v;
                out[b * NSTEP + st] = y;
                xcur[0] = y;
            }
        }
        __syncthreads();
    }
}

// ============================================================================
extern "C" void kernel_launch(void* const* d_in, const int* in_sizes, int n_in,
                              void* d_out, int out_size) {
    const float* x   = (const float*)d_in[0];
    const float* h0  = (const float*)d_in[1];
    const float* c0  = (const float*)d_in[2];
    const float* enc = (const float*)d_in[3];
    const float* Wa  = (const float*)d_in[4];
    const float* ba  = (const float*)d_in[5];
    const float* Ua  = (const float*)d_in[6];
    const float* bua = (const float*)d_in[7];
    const float* Va  = (const float*)d_in[8];
    const float* bva = (const float*)d_in[9];
    const float* Wih = (const float*)d_in[10];
    const float* Whh = (const float*)d_in[11];
    const float* bih = (const float*)d_in[12];
    const float* bhh = (const float*)d_in[13];
    const float* W1  = (const float*)d_in[14];
    const float* b1  = (const float*)d_in[15];
    const float* W2  = (const float*)d_in[16];
    const float* b2  = (const float*)d_in[17];
    const float* W3  = (const float*)d_in[18];
    const float* b3  = (const float*)d_in[19];
    float* out = (float*)d_out;

    cudaFuncSetAttribute(k_scores, cudaFuncAttributeMaxDynamicSharedMemorySize,
                         (int)SMEM_SC);
    cudaFuncSetAttribute(k_decode, cudaFuncAttributeMaxDynamicSharedMemorySize,
                         (int)SMEM_DEC);

    k_pre<<<dim3(5, NB), 256>>>(h0, Wa, ba, Whh, bhh);
    k_scores<<<NCTA, 512, SMEM_SC>>>(enc, Ua, bua, Va, bva);
    k_softctx<<<NB, 1024>>>(enc);
    k_gates<<<dim3(4, NB), 256>>>(Wih, bih);
    k_decode<<<NB, 256, SMEM_DEC>>>(x, c0, Wih, W1, b1, W2, b2, W3, b3, out);
}